// round 7
// baseline (speedup 1.0000x reference)
#include <cuda_runtime.h>
#include <cuda_fp16.h>
#include <math_constants.h>

#define BATCH 1024
#define NGENE 8192
#define NSETS 2048
#define MAX_TOTAL 262144   // >= 2048 * 120

// Scratch (static device globals — no runtime allocation)
__device__ __half g_GT[NGENE * BATCH];    // transposed features, fp16, 16.8 MB
__device__ float  g_outT[NSETS * BATCH];  // set-major output staging, 8.4 MB
__device__ float  g_w[MAX_TOTAL];         // softmax weights per edge
__device__ int    g_off[NSETS + 1];       // segment start offsets

// ---------------------------------------------------------------------------
// K2: warp-per-segment softmax; segment bounds via binary search on sorted
// segment_ids, published to g_off for k_agg.
// ---------------------------------------------------------------------------
__global__ void k_softmax(const float* __restrict__ logits,
                          const int* __restrict__ seg, int total) {
    int warp_id = (blockIdx.x * blockDim.x + threadIdx.x) >> 5;
    if (warp_id >= NSETS) return;
    int lane = threadIdx.x & 31;

    int lo = 0, hi = total;
    while (lo < hi) { int mid = (lo + hi) >> 1; if (seg[mid] < warp_id) lo = mid + 1; else hi = mid; }
    int beg = lo;
    hi = total;
    while (lo < hi) { int mid = (lo + hi) >> 1; if (seg[mid] < warp_id + 1) lo = mid + 1; else hi = mid; }
    int end = lo;

    if (lane == 0) {
        g_off[warp_id] = beg;
        if (warp_id == NSETS - 1) g_off[NSETS] = total;
    }

    float m = -CUDART_INF_F;
    for (int p = beg + lane; p < end; p += 32) m = fmaxf(m, logits[p]);
    #pragma unroll
    for (int o = 16; o; o >>= 1) m = fmaxf(m, __shfl_xor_sync(0xFFFFFFFFu, m, o));

    float sum = 0.0f;
    for (int p = beg + lane; p < end; p += 32) {
        float e = __expf(logits[p] - m);
        g_w[p] = e;
        sum += e;
    }
    #pragma unroll
    for (int o = 16; o; o >>= 1) sum += __shfl_xor_sync(0xFFFFFFFFu, sum, o);

    float inv = (sum > 0.0f) ? (1.0f / sum) : 0.0f;
    for (int p = beg + lane; p < end; p += 32) g_w[p] *= inv;
}

// ---------------------------------------------------------------------------
// K3: tiled transpose + fp16 convert: G(1024 x 8192) f32 -> GT(8192 x 1024) f16
// blockDim (32,8), grid (NGENE/32, BATCH/32)
// ---------------------------------------------------------------------------
__global__ void k_transpose(const float* __restrict__ G) {
    __shared__ float tile[32][33];
    int gx = blockIdx.x * 32;   // gene base
    int by = blockIdx.y * 32;   // batch base
    int x = gx + threadIdx.x;
    #pragma unroll
    for (int j = 0; j < 32; j += 8)
        tile[threadIdx.y + j][threadIdx.x] = G[(by + threadIdx.y + j) * NGENE + x];
    __syncthreads();
    #pragma unroll
    for (int j = 0; j < 32; j += 8)
        g_GT[(gx + threadIdx.y + j) * BATCH + by + threadIdx.x] =
            __float2half_rn(tile[threadIdx.x][threadIdx.y + j]);
}

// ---------------------------------------------------------------------------
// K4: block-per-set aggregation (grid = 2048, 256 threads), round-5 shape,
// PLUS a manual 4-deep register pipeline on the gather loads so >=4
// independent LDG.64 are always in flight per thread (ptxas wasn't batching).
// Thread t owns batch rows 4t..4t+3 (one uint2 = 4 halfs per edge).
// ---------------------------------------------------------------------------
__global__ __launch_bounds__(256) void k_agg(const int* __restrict__ flat_idx) {
    int s = blockIdx.x;
    int beg = g_off[s];
    int n = g_off[s + 1] - beg;
    if (n > 128) n = 128;   // structural: n <= 120

    __shared__ int   sh_idx[128];
    __shared__ float sh_w[128];
    int t = threadIdx.x;
    if (t < n) {
        sh_idx[t] = flat_idx[beg + t];
        sh_w[t]   = g_w[beg + t];
    }
    __syncthreads();

    const uint2* __restrict__ GT64 = reinterpret_cast<const uint2*>(g_GT);
    float4 acc = make_float4(0.f, 0.f, 0.f, 0.f);

    uint2 buf[4];
    #pragma unroll
    for (int i = 0; i < 4; i++)
        if (i < n) buf[i] = GT64[sh_idx[i] * (BATCH / 4) + t];

    #pragma unroll 4
    for (int i = 0; i < n; i++) {
        uint2 u = buf[i & 3];
        int j = i + 4;
        if (j < n) buf[i & 3] = GT64[sh_idx[j] * (BATCH / 4) + t];
        float w = sh_w[i];
        float2 v0 = __half22float2(*reinterpret_cast<const __half2*>(&u.x));
        float2 v1 = __half22float2(*reinterpret_cast<const __half2*>(&u.y));
        acc.x += w * v0.x;
        acc.y += w * v0.y;
        acc.z += w * v1.x;
        acc.w += w * v1.y;
    }

    reinterpret_cast<float4*>(g_outT + (size_t)s * BATCH)[t] = acc;
}

// ---------------------------------------------------------------------------
// K5: transpose outT(2048 x 1024) -> out(1024 x 2048), float4 on both
// global sides. blockDim (8,32), grid (BATCH/32, NSETS/32).
// Bank math: STS addr ~ ty + 4tx (mod 32) -> distinct per warp; LDS addr
// ~ (4tx+k) + ty (mod 32) -> distinct per warp. Conflict-free.
// ---------------------------------------------------------------------------
__global__ void k_out_transpose(float* __restrict__ out) {
    __shared__ float tile[32][33];
    int bx = blockIdx.x * 32;   // batch base
    int sy = blockIdx.y * 32;   // set base
    int tx = threadIdx.x;       // 0..7
    int ty = threadIdx.y;       // 0..31

    // Load: row = set sy+ty, 8 threads x float4 = 128B coalesced
    float4 v = reinterpret_cast<const float4*>(
                   g_outT + (size_t)(sy + ty) * BATCH + bx)[tx];
    tile[ty][4 * tx + 0] = v.x;
    tile[ty][4 * tx + 1] = v.y;
    tile[ty][4 * tx + 2] = v.z;
    tile[ty][4 * tx + 3] = v.w;
    __syncthreads();

    // Store: row = batch bx+ty, cols sy+4tx..+3 as one float4; 8 threads
    // per row = 128B coalesced
    float4 o;
    o.x = tile[4 * tx + 0][ty];
    o.y = tile[4 * tx + 1][ty];
    o.z = tile[4 * tx + 2][ty];
    o.w = tile[4 * tx + 3][ty];
    reinterpret_cast<float4*>(out + (size_t)(bx + ty) * NSETS + sy)[tx] = o;
}

// ---------------------------------------------------------------------------
// Launcher (graph-capturable: kernel launches only, default stream ordering)
// ---------------------------------------------------------------------------
extern "C" void kernel_launch(void* const* d_in, const int* in_sizes, int n_in,
                              void* d_out, int out_size) {
    const float* G      = (const float*)d_in[0];
    const float* logits = (const float*)d_in[1];
    const int*   fidx   = (const int*)d_in[2];
    const int*   seg    = (const int*)d_in[3];
    float*       out    = (float*)d_out;
    int total = in_sizes[1];

    k_softmax<<<(NSETS * 32 + 255) / 256, 256>>>(logits, seg, total);
    k_transpose<<<dim3(NGENE / 32, BATCH / 32), dim3(32, 8)>>>(G);
    k_agg<<<NSETS, 256>>>(fidx);
    k_out_transpose<<<dim3(BATCH / 32, NSETS / 32), dim3(8, 32)>>>(out);
}

// round 8
// speedup vs baseline: 1.1737x; 1.1737x over previous
#include <cuda_runtime.h>
#include <cuda_fp16.h>
#include <math_constants.h>

#define BATCH 1024
#define NGENE 8192
#define NSETS 2048
#define MAX_TOTAL 262144   // >= 2048 * 120

// Scratch (static device globals — no runtime allocation)
__device__ __half g_GT[NGENE * BATCH];    // transposed features, fp16, 16.8 MB
__device__ float  g_outT[NSETS * BATCH];  // set-major output staging, 8.4 MB
__device__ float  g_w[MAX_TOTAL];         // softmax weights per edge
__device__ int    g_off[NSETS + 1];       // segment start offsets

// ---------------------------------------------------------------------------
// K2: warp-per-segment softmax; segment bounds via binary search on sorted
// segment_ids, published to g_off for k_agg.
// ---------------------------------------------------------------------------
__global__ void k_softmax(const float* __restrict__ logits,
                          const int* __restrict__ seg, int total) {
    int warp_id = (blockIdx.x * blockDim.x + threadIdx.x) >> 5;
    if (warp_id >= NSETS) return;
    int lane = threadIdx.x & 31;

    int lo = 0, hi = total;
    while (lo < hi) { int mid = (lo + hi) >> 1; if (seg[mid] < warp_id) lo = mid + 1; else hi = mid; }
    int beg = lo;
    hi = total;
    while (lo < hi) { int mid = (lo + hi) >> 1; if (seg[mid] < warp_id + 1) lo = mid + 1; else hi = mid; }
    int end = lo;

    if (lane == 0) {
        g_off[warp_id] = beg;
        if (warp_id == NSETS - 1) g_off[NSETS] = total;
    }

    float m = -CUDART_INF_F;
    for (int p = beg + lane; p < end; p += 32) m = fmaxf(m, logits[p]);
    #pragma unroll
    for (int o = 16; o; o >>= 1) m = fmaxf(m, __shfl_xor_sync(0xFFFFFFFFu, m, o));

    float sum = 0.0f;
    for (int p = beg + lane; p < end; p += 32) {
        float e = __expf(logits[p] - m);
        g_w[p] = e;
        sum += e;
    }
    #pragma unroll
    for (int o = 16; o; o >>= 1) sum += __shfl_xor_sync(0xFFFFFFFFu, sum, o);

    float inv = (sum > 0.0f) ? (1.0f / sum) : 0.0f;
    for (int p = beg + lane; p < end; p += 32) g_w[p] *= inv;
}

// ---------------------------------------------------------------------------
// K3: transpose + fp16 convert, 4 tiles per block.
// G(1024 x 8192) f32 -> GT(8192 x 1024) f16.
// blockDim (8,32), grid (NGENE/128, BATCH/32). Per tile k:
//   load : thread(tx,ty) reads float4 G[by+ty][gx+32k+4tx .. +3]  (128B/warp-row)
//   store: thread(tx,ty) writes 4 halfs GT[gx+32k+ty][by+4tx .. +3] (uint2)
// Bank check (33-stride tile): (4tx+ty+j) mod 32 distinct per warp, both phases.
// ---------------------------------------------------------------------------
__global__ void k_transpose(const float* __restrict__ G) {
    __shared__ float tile[4][32][33];
    int gx = blockIdx.x * 128;
    int by = blockIdx.y * 32;
    int tx = threadIdx.x;   // 0..7
    int ty = threadIdx.y;   // 0..31

    #pragma unroll
    for (int k = 0; k < 4; k++) {
        float4 v = reinterpret_cast<const float4*>(
                       G + (size_t)(by + ty) * NGENE + gx + 32 * k)[tx];
        tile[k][4 * tx + 0][ty] = v.x;
        tile[k][4 * tx + 1][ty] = v.y;
        tile[k][4 * tx + 2][ty] = v.z;
        tile[k][4 * tx + 3][ty] = v.w;
    }
    __syncthreads();

    #pragma unroll
    for (int k = 0; k < 4; k++) {
        __half2 h01 = __floats2half2_rn(tile[k][ty][4 * tx + 0],
                                        tile[k][ty][4 * tx + 1]);
        __half2 h23 = __floats2half2_rn(tile[k][ty][4 * tx + 2],
                                        tile[k][ty][4 * tx + 3]);
        uint2 u;
        u.x = *reinterpret_cast<unsigned*>(&h01);
        u.y = *reinterpret_cast<unsigned*>(&h23);
        *reinterpret_cast<uint2*>(
            g_GT + (size_t)(gx + 32 * k + ty) * BATCH + by + 4 * tx) = u;
    }
}

// ---------------------------------------------------------------------------
// K4: block-per-set aggregation (grid = 2048, 256 threads), round-5 shape,
// with an explicit branch-free 4-wide main loop: 4 unconditional LDG.64s
// issued back-to-back per iteration, then 16 FFMAs. Scalar remainder.
// Thread t owns batch rows 4t..4t+3 (one uint2 = 4 halfs per edge).
// ---------------------------------------------------------------------------
__global__ __launch_bounds__(256) void k_agg(const int* __restrict__ flat_idx) {
    int s = blockIdx.x;
    int beg = g_off[s];
    int n = g_off[s + 1] - beg;
    if (n > 128) n = 128;   // structural: n <= 120

    __shared__ int   sh_idx[128];
    __shared__ float sh_w[128];
    int t = threadIdx.x;
    if (t < n) {
        sh_idx[t] = flat_idx[beg + t];
        sh_w[t]   = g_w[beg + t];
    }
    __syncthreads();

    const uint2* __restrict__ GT64 = reinterpret_cast<const uint2*>(g_GT);
    float4 acc = make_float4(0.f, 0.f, 0.f, 0.f);

    int i = 0;
    for (; i + 4 <= n; i += 4) {
        uint2 u0 = GT64[sh_idx[i + 0] * (BATCH / 4) + t];
        uint2 u1 = GT64[sh_idx[i + 1] * (BATCH / 4) + t];
        uint2 u2 = GT64[sh_idx[i + 2] * (BATCH / 4) + t];
        uint2 u3 = GT64[sh_idx[i + 3] * (BATCH / 4) + t];
        float w0 = sh_w[i + 0], w1 = sh_w[i + 1];
        float w2 = sh_w[i + 2], w3 = sh_w[i + 3];
        float2 v;
        v = __half22float2(*reinterpret_cast<const __half2*>(&u0.x));
        acc.x += w0 * v.x;  acc.y += w0 * v.y;
        v = __half22float2(*reinterpret_cast<const __half2*>(&u0.y));
        acc.z += w0 * v.x;  acc.w += w0 * v.y;
        v = __half22float2(*reinterpret_cast<const __half2*>(&u1.x));
        acc.x += w1 * v.x;  acc.y += w1 * v.y;
        v = __half22float2(*reinterpret_cast<const __half2*>(&u1.y));
        acc.z += w1 * v.x;  acc.w += w1 * v.y;
        v = __half22float2(*reinterpret_cast<const __half2*>(&u2.x));
        acc.x += w2 * v.x;  acc.y += w2 * v.y;
        v = __half22float2(*reinterpret_cast<const __half2*>(&u2.y));
        acc.z += w2 * v.x;  acc.w += w2 * v.y;
        v = __half22float2(*reinterpret_cast<const __half2*>(&u3.x));
        acc.x += w3 * v.x;  acc.y += w3 * v.y;
        v = __half22float2(*reinterpret_cast<const __half2*>(&u3.y));
        acc.z += w3 * v.x;  acc.w += w3 * v.y;
    }
    for (; i < n; i++) {
        uint2 u = GT64[sh_idx[i] * (BATCH / 4) + t];
        float w = sh_w[i];
        float2 v0 = __half22float2(*reinterpret_cast<const __half2*>(&u.x));
        float2 v1 = __half22float2(*reinterpret_cast<const __half2*>(&u.y));
        acc.x += w * v0.x;
        acc.y += w * v0.y;
        acc.z += w * v1.x;
        acc.w += w * v1.y;
    }

    reinterpret_cast<float4*>(g_outT + (size_t)s * BATCH)[t] = acc;
}

// ---------------------------------------------------------------------------
// K5: transpose outT(2048 x 1024) -> out(1024 x 2048), 4 tiles per block.
// blockDim (8,32), grid (BATCH/128, NSETS/32) = 512 blocks. All 4 tile
// loads (float4) issued before the single sync -> 4x per-block MLP.
// ---------------------------------------------------------------------------
__global__ void k_out_transpose(float* __restrict__ out) {
    __shared__ float tile[4][32][33];
    int bx = blockIdx.x * 128;  // batch base, 4 tiles of 32
    int sy = blockIdx.y * 32;   // set base
    int tx = threadIdx.x;       // 0..7
    int ty = threadIdx.y;       // 0..31

    #pragma unroll
    for (int k = 0; k < 4; k++) {
        float4 v = reinterpret_cast<const float4*>(
                       g_outT + (size_t)(sy + ty) * BATCH + bx + 32 * k)[tx];
        tile[k][4 * tx + 0][ty] = v.x;
        tile[k][4 * tx + 1][ty] = v.y;
        tile[k][4 * tx + 2][ty] = v.z;
        tile[k][4 * tx + 3][ty] = v.w;
    }
    __syncthreads();

    #pragma unroll
    for (int k = 0; k < 4; k++) {
        float4 o;
        o.x = tile[k][ty][4 * tx + 0];
        o.y = tile[k][ty][4 * tx + 1];
        o.z = tile[k][ty][4 * tx + 2];
        o.w = tile[k][ty][4 * tx + 3];
        reinterpret_cast<float4*>(
            out + (size_t)(bx + 32 * k + ty) * NSETS + sy)[tx] = o;
    }
}

// ---------------------------------------------------------------------------
// Launcher (graph-capturable: kernel launches only, default stream ordering)
// ---------------------------------------------------------------------------
extern "C" void kernel_launch(void* const* d_in, const int* in_sizes, int n_in,
                              void* d_out, int out_size) {
    const float* G      = (const float*)d_in[0];
    const float* logits = (const float*)d_in[1];
    const int*   fidx   = (const int*)d_in[2];
    const int*   seg    = (const int*)d_in[3];
    float*       out    = (float*)d_out;
    int total = in_sizes[1];

    k_softmax<<<(NSETS * 32 + 255) / 256, 256>>>(logits, seg, total);
    k_transpose<<<dim3(NGENE / 128, BATCH / 32), dim3(8, 32)>>>(G);
    k_agg<<<NSETS, 256>>>(fidx);
    k_out_transpose<<<dim3(BATCH / 128, NSETS / 32), dim3(8, 32)>>>(out);
}